// round 16
// baseline (speedup 1.0000x reference)
#include <cuda_runtime.h>
#include <cuda_bf16.h>
#include <cstdint>
#include <cstddef>

// Problem constants
#define BB 2
#define CC 128
#define NN 8192
#define KK 16
#define O1 128
#define O2 256
#define EPSF 1e-5f
#define SLOPE 0.2f

typedef __nv_bfloat16 bf16;

// ---------------- scratch (device globals; no allocation allowed) ----------------
static __device__ float4 g_pts4[BB * NN];
static __device__ int    g_idx[BB * NN * KK];
static __device__ bf16   g_W1h[256 * 128], g_W1l[256 * 128];
static __device__ bf16   g_W2h[512 * 128], g_W2l[512 * 128];
static __device__ bf16   g_W3h[128 * 512], g_W3l[128 * 512];
// unified activation buffer, n-major: [b][n][0:128 x0 | 128:256 x1 | 256:512 x2]
static __device__ bf16   g_XTh[(size_t)BB * NN * 512];
static __device__ bf16   g_XTl[(size_t)BB * NN * 512];
static __device__ float  g_G1[(size_t)BB * NN * 256];
static __device__ float  g_G2[(size_t)BB * NN * 512];
static __device__ float  g_M1[(size_t)BB * NN * 128];
static __device__ float  g_M2[(size_t)BB * NN * 256];
static __device__ float  g_G3[(size_t)BB * 128 * NN];
static __device__ float  g_sum1[BB * O1], g_sqs1[BB * O1];
static __device__ float  g_sum2[BB * O2], g_sqs2[BB * O2];
static __device__ float  g_sum3[BB * 128], g_sqs3[BB * 128];

__device__ __forceinline__ float leakyf(float v) { return v > 0.0f ? v : SLOPE * v; }

__device__ __forceinline__ void bsplit(float v, bf16& h, bf16& l) {
    h = __float2bfloat16(v);
    l = __float2bfloat16(v - __bfloat162float(h));
}

__device__ __forceinline__ void ldsm4(uint32_t* r, uint32_t addr) {
    asm volatile("ldmatrix.sync.aligned.m8n8.x4.shared.b16 {%0,%1,%2,%3}, [%4];"
        : "=r"(r[0]), "=r"(r[1]), "=r"(r[2]), "=r"(r[3]) : "r"(addr));
}

__device__ __forceinline__ void cpa16(uint32_t dst, const void* src) {
    asm volatile("cp.async.cg.shared.global [%0], [%1], 16;" :: "r"(dst), "l"(src));
}
#define CP_COMMIT() asm volatile("cp.async.commit_group;" ::: "memory")

// ---------------- prep: split weights + zero stats + pack points ----------------
__global__ void k_prep(const float* __restrict__ W1, const float* __restrict__ W2,
                       const float* __restrict__ W3, const float* __restrict__ coords) {
    int t = blockIdx.x * blockDim.x + threadIdx.x;
    if (t < 256 * 128) {
        int o = t >> 7, c = t & 127;
        float v = (o < 128) ? (W1[o * 256 + c] - W1[o * 256 + 128 + c])
                            : W1[(o - 128) * 256 + 128 + c];
        bsplit(v, g_W1h[t], g_W1l[t]);
    }
    if (t < 512 * 128) {
        int o = t >> 7, c = t & 127;
        float v = (o < 256) ? (W2[o * 256 + c] - W2[o * 256 + 128 + c])
                            : W2[(o - 256) * 256 + 128 + c];
        bsplit(v, g_W2h[t], g_W2l[t]);
        bsplit(W3[t], g_W3h[t], g_W3l[t]);
    }
    if (t < BB * NN) {
        int b = t >> 13, n = t & (NN - 1);
        const float* base = coords + (size_t)b * 3 * NN;
        float x = base[n], y = base[NN + n], z = base[2 * NN + n];
        g_pts4[t] = make_float4(x, y, z, x * x + y * y + z * z);
    }
    if (t < BB * O1) { g_sum1[t] = 0.0f; g_sqs1[t] = 0.0f; }
    if (t < BB * O2) { g_sum2[t] = 0.0f; g_sqs2[t] = 0.0f; }
    if (t < BB * 128) { g_sum3[t] = 0.0f; g_sqs3[t] = 0.0f; }
}

// ---------------- transpose+split x0: feats [b][c][n] -> XT[b][n][c] ----------------
__global__ void k_trans_x0(const float* __restrict__ feats) {
    __shared__ float t[32][33];
    int b = blockIdx.z, n0 = blockIdx.x * 32, c0 = blockIdx.y * 32;
    int tx = threadIdx.x, ty = threadIdx.y;
#pragma unroll
    for (int i = 0; i < 4; i++) {
        int c = c0 + ty + i * 8;
        t[ty + i * 8][tx] = feats[((size_t)b * CC + c) * NN + n0 + tx];
    }
    __syncthreads();
#pragma unroll
    for (int i = 0; i < 4; i++) {
        int n = n0 + ty + i * 8;
        float v = t[tx][ty + i * 8];
        size_t o = ((size_t)b * NN + n) * 512 + c0 + tx;
        bf16 h, l;
        bsplit(v, h, l);
        g_XTh[o] = h;
        g_XTl[o] = l;
    }
}

// ---------------- warp-collective kNN: 2 queries per warp, 8 warps/block, 1024 tile ----------------
// Self-exclusion hoisted out of the hot loop: d_self = -|q|^2 is the global minimum,
// so self always passes d<thr; it is rejected once in the (rare) insert path.
#define KNN_TS 1024
#define KNN_WPB 8
#define KNN_QPW 2

__global__ void __launch_bounds__(KNN_WPB * 32) k_knn() {
    __shared__ float4 sp[KNN_TS];
    const unsigned FULL = 0xFFFFFFFFu;
    int lane = threadIdx.x & 31;
    int wid = threadIdx.x >> 5;
    int gq0 = (blockIdx.x * KNN_WPB + wid) * KNN_QPW;
    int b = gq0 >> 13;
    int qi0 = gq0 & (NN - 1);

    float4 myq = g_pts4[b * NN + qi0 + (lane & (KNN_QPW - 1))];
    float qx2[KNN_QPW], qy2[KNN_QPW], qz2[KNN_QPW];
    int qid[KNN_QPW];
#pragma unroll
    for (int j = 0; j < KNN_QPW; j++) {
        qx2[j] = -2.0f * __shfl_sync(FULL, myq.x, j);
        qy2[j] = -2.0f * __shfl_sync(FULL, myq.y, j);
        qz2[j] = -2.0f * __shfl_sync(FULL, myq.z, j);
        qid[j] = qi0 + j;
    }

    const float INFF = __int_as_float(0x7f800000);
    float dcur[KNN_QPW]; int icur[KNN_QPW]; float thr[KNN_QPW];
#pragma unroll
    for (int j = 0; j < KNN_QPW; j++) { dcur[j] = INFF; icur[j] = 0; thr[j] = INFF; }

    for (int c0 = 0; c0 < NN; c0 += KNN_TS) {
        __syncthreads();
#pragma unroll
        for (int r = 0; r < KNN_TS / (KNN_WPB * 32); r++)
            sp[r * (KNN_WPB * 32) + threadIdx.x] =
                g_pts4[b * NN + c0 + r * (KNN_WPB * 32) + threadIdx.x];
        __syncthreads();

#pragma unroll 2
        for (int t0 = 0; t0 < KNN_TS; t0 += 32) {
            float4 p = sp[t0 + lane];
            int jg = c0 + t0 + lane;
#pragma unroll
            for (int j = 0; j < KNN_QPW; j++) {
                float d = fmaf(qx2[j], p.x, p.w);
                d = fmaf(qy2[j], p.y, d);
                d = fmaf(qz2[j], p.z, d);
                unsigned m = __ballot_sync(FULL, d < thr[j]);
                while (m) {
                    int src = __ffs(m) - 1;
                    m &= m - 1;
                    float v = __shfl_sync(FULL, d, src);
                    int  vi = __shfl_sync(FULL, jg, src);
                    if (v < thr[j] && vi != qid[j]) {
                        unsigned stay = __ballot_sync(FULL, (lane < 16) && (dcur[j] <= v));
                        int pos = __popc(stay);
                        float pd = __shfl_up_sync(FULL, dcur[j], 1);
                        int   pi = __shfl_up_sync(FULL, icur[j], 1);
                        if (lane < 16 && lane >= pos) {
                            dcur[j] = (lane == pos) ? v : pd;
                            icur[j] = (lane == pos) ? vi : pi;
                        }
                        thr[j] = __shfl_sync(FULL, dcur[j], 15);
                    }
                }
            }
        }
    }

    if (lane < 16) {
#pragma unroll
        for (int j = 0; j < KNN_QPW; j++)
            g_idx[((size_t)b * NN + qi0 + j) * KK + lane] = icur[j];
    }
}

// ---------------- tensor-core GEMM: 128m x 64n tile, cp.async 3-stage, split-bf16 x3 ----------------
// KDW: W row stride. KDI: iterated K width. ACCUM: add into Out (stats on the sum).
#define MPAD 40
#define NST 3
#define ASTG (128 * MPAD * 2)          // A stage bytes
#define BSTG (64 * MPAD * 2)           // B stage bytes
#define MMA_SMEM (NST * (ASTG + BSTG)) // 46080 B

template <bool OUTNM, int KDW, int KDI, bool STATS, bool ACCUM>
__global__ void __launch_bounds__(256) k_mma(
        const bf16* __restrict__ Wh, const bf16* __restrict__ Wl,
        const bf16* __restrict__ Xh, const bf16* __restrict__ Xl,
        float* __restrict__ Out, int M, int kOff, size_t oStride,
        float* __restrict__ sums, float* __restrict__ sqs) {
    constexpr int SL = KDI / 32;
    constexpr int TOT = 3 * SL;
    extern __shared__ bf16 dynsm[];
    bf16* As = dynsm;                            // [NST][128][MPAD]
    bf16* Bs = dynsm + NST * 128 * MPAD;         // [NST][64][MPAD]
    __shared__ float sSum[128], sSq[128];

    int tid = threadIdx.x;
    int lane = tid & 31;
    int wid = tid >> 5;
    int wm = wid & 1, wn = wid >> 1;             // warp tile: 64m x 16n
    int b = blockIdx.z;
    int m0 = blockIdx.y * 128, n0 = blockIdx.x * 64;

    int arow = tid >> 1, acolq = (tid & 1) * 16;
    int brow = tid >> 2, bcol = (tid & 3) * 8;
    int lr15 = lane & 15, lh8 = (lane >> 4) * 8;

    uint32_t aBase = (uint32_t)__cvta_generic_to_shared(As);
    uint32_t bBase = (uint32_t)__cvta_generic_to_shared(Bs);
    uint32_t wdst0 = aBase + (arow * MPAD + acolq) * 2;
    uint32_t xdst0 = bBase + (brow * MPAD + bcol) * 2;

    const bf16* wRowH = &Wh[(size_t)(m0 + arow) * KDW + acolq];
    const bf16* wRowL = &Wl[(size_t)(m0 + arow) * KDW + acolq];
    const bf16* xRowH = &Xh[((size_t)b * NN + n0 + brow) * 512 + kOff + bcol];
    const bf16* xRowL = &Xl[((size_t)b * NN + n0 + brow) * 512 + kOff + bcol];

    auto issue = [&](int s) {
        int seg = s / SL, k0 = (s % SL) * 32;
        const bf16* wsrc = ((seg == 1) ? wRowL : wRowH) + k0;
        const bf16* xsrc = ((seg == 2) ? xRowL : xRowH) + k0;
        uint32_t offA = (uint32_t)((s % NST) * ASTG);
        uint32_t offB = (uint32_t)((s % NST) * BSTG);
        cpa16(wdst0 + offA, wsrc);
        cpa16(wdst0 + offA + 16, wsrc + 8);
        cpa16(xdst0 + offB, xsrc);
    };

    float acc[4][2][4];
#pragma unroll
    for (int i = 0; i < 4; i++)
#pragma unroll
        for (int j = 0; j < 2; j++)
#pragma unroll
            for (int r = 0; r < 4; r++) acc[i][j][r] = 0.0f;

    if (STATS && tid < 128) { sSum[tid] = 0.0f; sSq[tid] = 0.0f; }

    issue(0); CP_COMMIT();
    issue(1); CP_COMMIT();

    for (int s = 0; s < TOT; s++) {
        __syncthreads();                    // buffer (s+2)%NST free (computed at s-1)
        if (s + 2 < TOT) issue(s + 2);
        CP_COMMIT();
        asm volatile("cp.async.wait_group 2;" ::: "memory");   // stage s resident
        __syncthreads();

        uint32_t aB = aBase + (uint32_t)((s % NST) * ASTG);
        uint32_t bB = bBase + (uint32_t)((s % NST) * BSTG);
#pragma unroll
        for (int ks = 0; ks < 2; ks++) {
            uint32_t af[4][4];
#pragma unroll
            for (int i = 0; i < 4; i++) {
                uint32_t addr = aB + ((wm * 64 + i * 16 + lr15) * MPAD + lh8 + ks * 16) * 2;
                ldsm4(af[i], addr);
            }
            uint32_t bfr[4];
            {
                uint32_t addr = bB + ((wn * 16 + lr15) * MPAD + lh8 + ks * 16) * 2;
                ldsm4(bfr, addr);
            }
#pragma unroll
            for (int i = 0; i < 4; i++)
#pragma unroll
                for (int j = 0; j < 2; j++) {
                    asm volatile(
                        "mma.sync.aligned.m16n8k16.row.col.f32.bf16.bf16.f32 "
                        "{%0,%1,%2,%3}, {%4,%5,%6,%7}, {%8,%9}, {%0,%1,%2,%3};"
                        : "+f"(acc[i][j][0]), "+f"(acc[i][j][1]),
                          "+f"(acc[i][j][2]), "+f"(acc[i][j][3])
                        : "r"(af[i][0]), "r"(af[i][1]), "r"(af[i][2]), "r"(af[i][3]),
                          "r"(bfr[j]), "r"(bfr[j + 2]));
                }
        }
    }

    int g = lane >> 2, tq = lane & 3;
    float* Ob = Out + (size_t)b * oStride;
    if (OUTNM) {
#pragma unroll
        for (int i = 0; i < 4; i++) {
            int m = m0 + wm * 64 + i * 16 + g;
#pragma unroll
            for (int j = 0; j < 2; j++) {
                int n = n0 + wn * 16 + j * 8 + 2 * tq;
                Ob[(size_t)n * M + m] = acc[i][j][0];
                Ob[(size_t)(n + 1) * M + m] = acc[i][j][1];
                Ob[(size_t)n * M + m + 8] = acc[i][j][2];
                Ob[(size_t)(n + 1) * M + m + 8] = acc[i][j][3];
            }
        }
    } else {
#pragma unroll
        for (int i = 0; i < 4; i++) {
            int m = m0 + wm * 64 + i * 16 + g;
#pragma unroll
            for (int j = 0; j < 2; j++) {
                int n = n0 + wn * 16 + j * 8 + 2 * tq;
                float2 v01 = make_float2(acc[i][j][0], acc[i][j][1]);
                float2 v23 = make_float2(acc[i][j][2], acc[i][j][3]);
                if (ACCUM) {
                    float2 o01 = *(float2*)&Ob[(size_t)m * NN + n];
                    float2 o23 = *(float2*)&Ob[(size_t)(m + 8) * NN + n];
                    v01.x += o01.x; v01.y += o01.y;
                    v23.x += o23.x; v23.y += o23.y;
                }
                *(float2*)&Ob[(size_t)m * NN + n] = v01;
                *(float2*)&Ob[(size_t)(m + 8) * NN + n] = v23;
                if (STATS) {
                    acc[i][j][0] = v01.x; acc[i][j][1] = v01.y;
                    acc[i][j][2] = v23.x; acc[i][j][3] = v23.y;
                }
            }
        }
    }

    if (STATS) {
        const unsigned FULL = 0xFFFFFFFFu;
#pragma unroll
        for (int i = 0; i < 4; i++) {
            float s0 = 0.0f, q0 = 0.0f, s1 = 0.0f, q1 = 0.0f;
#pragma unroll
            for (int j = 0; j < 2; j++) {
                float a0 = acc[i][j][0], a1 = acc[i][j][1];
                float a2 = acc[i][j][2], a3 = acc[i][j][3];
                s0 += a0 + a1;
                q0 = fmaf(a0, a0, q0); q0 = fmaf(a1, a1, q0);
                s1 += a2 + a3;
                q1 = fmaf(a2, a2, q1); q1 = fmaf(a3, a3, q1);
            }
#pragma unroll
            for (int sh = 1; sh < 4; sh <<= 1) {
                s0 += __shfl_xor_sync(FULL, s0, sh);
                q0 += __shfl_xor_sync(FULL, q0, sh);
                s1 += __shfl_xor_sync(FULL, s1, sh);
                q1 += __shfl_xor_sync(FULL, q1, sh);
            }
            if (tq == 0) {
                int r = wm * 64 + i * 16 + g;
                atomicAdd(&sSum[r], s0);
                atomicAdd(&sSq[r], q0);
                atomicAdd(&sSum[r + 8], s1);
                atomicAdd(&sSq[r + 8], q1);
            }
        }
        __syncthreads();
        if (tid < 128) {
            atomicAdd(&sums[b * 128 + m0 + tid], sSum[tid]);
            atomicAdd(&sqs[b * 128 + m0 + tid], sSq[tid]);
        }
    }
}

// ---------------- edge layer (float4): y = A[n,:] + B[idx[n,k],:]; max over k + stats ----------------
template <int O>
__global__ void k_edge(const float* __restrict__ G, const int* __restrict__ idx,
                       float* __restrict__ Mout, float* __restrict__ sums,
                       float* __restrict__ sqs) {
    constexpr int TX = O / 4;
    constexpr int TY = 512 / TX;
    constexpr int NPB = 64;
    int b = blockIdx.y;
    int n0 = blockIdx.x * NPB;
    int tx = threadIdx.x, ty = threadIdx.y;
    float4 lsum = make_float4(0, 0, 0, 0), lsq = make_float4(0, 0, 0, 0);
    const float NEGINF = __int_as_float(0xff800000);

    for (int n = n0 + ty; n < n0 + NPB; n += TY) {
        size_t rowb = (size_t)b * NN + n;
        float4 a = *(const float4*)&G[rowb * (2 * O) + 4 * tx];
        const int4* I4 = (const int4*)(idx + rowb * KK);
        int4 iv[4] = { I4[0], I4[1], I4[2], I4[3] };
        const int* I = (const int*)iv;
        float4 mx = make_float4(NEGINF, NEGINF, NEGINF, NEGINF);
#pragma unroll
        for (int k = 0; k < KK; k++) {
            int j = I[k];
            float4 bv = *(const float4*)&G[((size_t)b * NN + j) * (2 * O) + O + 4 * tx];
            float4 v = make_float4(a.x + bv.x, a.y + bv.y, a.z + bv.z, a.w + bv.w);
            mx.x = fmaxf(mx.x, v.x); mx.y = fmaxf(mx.y, v.y);
            mx.z = fmaxf(mx.z, v.z); mx.w = fmaxf(mx.w, v.w);
            lsum.x += v.x; lsum.y += v.y; lsum.z += v.z; lsum.w += v.w;
            lsq.x = fmaf(v.x, v.x, lsq.x); lsq.y = fmaf(v.y, v.y, lsq.y);
            lsq.z = fmaf(v.z, v.z, lsq.z); lsq.w = fmaf(v.w, v.w, lsq.w);
        }
        *(float4*)&Mout[rowb * O + 4 * tx] = mx;
    }
    __shared__ float4 s1[TY][TX], s2[TY][TX];
    s1[ty][tx] = lsum; s2[ty][tx] = lsq;
    __syncthreads();
    if (ty == 0) {
        float4 t1 = lsum, t2 = lsq;
#pragma unroll
        for (int t = 1; t < TY; t++) {
            float4 u1 = s1[t][tx], u2 = s2[t][tx];
            t1.x += u1.x; t1.y += u1.y; t1.z += u1.z; t1.w += u1.w;
            t2.x += u2.x; t2.y += u2.y; t2.z += u2.z; t2.w += u2.w;
        }
        atomicAdd(&sums[b * O + 4 * tx + 0], t1.x);
        atomicAdd(&sums[b * O + 4 * tx + 1], t1.y);
        atomicAdd(&sums[b * O + 4 * tx + 2], t1.z);
        atomicAdd(&sums[b * O + 4 * tx + 3], t1.w);
        atomicAdd(&sqs[b * O + 4 * tx + 0], t2.x);
        atomicAdd(&sqs[b * O + 4 * tx + 1], t2.y);
        atomicAdd(&sqs[b * O + 4 * tx + 2], t2.z);
        atomicAdd(&sqs[b * O + 4 * tx + 3], t2.w);
    }
}

// ---------------- normalize + leaky + bf16-split (stats inline): Min[b][n][O] -> XT ----------------
__global__ void k_normsplit(const float* __restrict__ Min, const float* __restrict__ sums,
                            const float* __restrict__ sqs, int O, int obase, float invcnt) {
    size_t t = (size_t)blockIdx.x * blockDim.x + threadIdx.x;
    if (t >= (size_t)BB * NN * O / 4) return;
    int o4 = (int)(t % (O / 4));
    size_t bn = t / (O / 4);
    int b = (int)(bn >> 13);
    float4 v = ((const float4*)Min)[t];
    float vv[4] = { v.x, v.y, v.z, v.w };
    bf16 h4[4], l4[4];
#pragma unroll
    for (int c = 0; c < 4; c++) {
        int o = 4 * o4 + c;
        float m = sums[b * O + o] * invcnt;
        float var = sqs[b * O + o] * invcnt - m * m;
        float iv = rsqrtf(var + EPSF);
        float y = leakyf((vv[c] - m) * iv);
        bsplit(y, h4[c], l4[c]);
    }
    size_t dst = bn * 512 + obase + 4 * o4;
    *(uint2*)&g_XTh[dst] = *(uint2*)h4;
    *(uint2*)&g_XTl[dst] = *(uint2*)l4;
}

// ---------------- final normalize + leaky -> output [B,C,N] ----------------
__global__ void k_final(float* __restrict__ out) {
    size_t t = (size_t)blockIdx.x * blockDim.x + threadIdx.x;
    if (t >= (size_t)BB * 128 * NN / 4) return;
    int bo = (int)(t / (NN / 4));
    float m = g_sum3[bo] * (1.0f / NN);
    float var = g_sqs3[bo] * (1.0f / NN) - m * m;
    float iv = rsqrtf(var + EPSF);
    float4 v = ((const float4*)g_G3)[t];
    v.x = leakyf((v.x - m) * iv);
    v.y = leakyf((v.y - m) * iv);
    v.z = leakyf((v.z - m) * iv);
    v.w = leakyf((v.w - m) * iv);
    ((float4*)out)[t] = v;
}

// ---------------- launch ----------------
extern "C" void kernel_launch(void* const* d_in, const int* in_sizes, int n_in,
                              void* d_out, int out_size) {
    const float* coords = (const float*)d_in[0];
    const float* feats  = (const float*)d_in[1];
    const float* W1     = (const float*)d_in[2];
    const float* W2     = (const float*)d_in[3];
    const float* W3     = (const float*)d_in[4];
    float* out = (float*)d_out;

    cudaFuncSetAttribute(k_knn, cudaFuncAttributePreferredSharedMemoryCarveout,
                         cudaSharedmemCarveoutMaxShared);
    cudaFuncSetAttribute(k_mma<true, 128, 128, false, false>,
                         cudaFuncAttributeMaxDynamicSharedMemorySize, MMA_SMEM);
    cudaFuncSetAttribute(k_mma<false, 512, 128, false, false>,
                         cudaFuncAttributeMaxDynamicSharedMemorySize, MMA_SMEM);
    cudaFuncSetAttribute(k_mma<false, 512, 384, true, true>,
                         cudaFuncAttributeMaxDynamicSharedMemorySize, MMA_SMEM);

    float *pG1, *pG2, *pM1, *pM2, *pG3;
    int* pIdx;
    float *pSum1, *pSqs1, *pSum2, *pSqs2, *pSum3, *pSqs3;
    bf16 *pW1h, *pW1l, *pW2h, *pW2l, *pW3h, *pW3l, *pXTh, *pXTl;
    cudaGetSymbolAddress((void**)&pG1, g_G1);
    cudaGetSymbolAddress((void**)&pG2, g_G2);
    cudaGetSymbolAddress((void**)&pM1, g_M1);
    cudaGetSymbolAddress((void**)&pM2, g_M2);
    cudaGetSymbolAddress((void**)&pG3, g_G3);
    cudaGetSymbolAddress((void**)&pIdx, g_idx);
    cudaGetSymbolAddress((void**)&pSum1, g_sum1);
    cudaGetSymbolAddress((void**)&pSqs1, g_sqs1);
    cudaGetSymbolAddress((void**)&pSum2, g_sum2);
    cudaGetSymbolAddress((void**)&pSqs2, g_sqs2);
    cudaGetSymbolAddress((void**)&pSum3, g_sum3);
    cudaGetSymbolAddress((void**)&pSqs3, g_sqs3);
    cudaGetSymbolAddress((void**)&pW1h, g_W1h);
    cudaGetSymbolAddress((void**)&pW1l, g_W1l);
    cudaGetSymbolAddress((void**)&pW2h, g_W2h);
    cudaGetSymbolAddress((void**)&pW2l, g_W2l);
    cudaGetSymbolAddress((void**)&pW3h, g_W3h);
    cudaGetSymbolAddress((void**)&pW3l, g_W3l);
    cudaGetSymbolAddress((void**)&pXTh, g_XTh);
    cudaGetSymbolAddress((void**)&pXTl, g_XTl);
    (void)in_sizes; (void)n_in; (void)out_size;

    // side stream + events for the parallel knn branch in the captured graph
    cudaStream_t s2;
    cudaEvent_t eFork, eKnn;
    cudaStreamCreateWithFlags(&s2, cudaStreamNonBlocking);
    cudaEventCreateWithFlags(&eFork, cudaEventDisableTiming);
    cudaEventCreateWithFlags(&eKnn, cudaEventDisableTiming);

    k_prep<<<256, 256>>>(W1, W2, W3, coords);

    // fork: knn runs concurrently with trans_x0 + mma1 + mma3-x0 partial
    cudaEventRecord(eFork, 0);
    cudaStreamWaitEvent(s2, eFork, 0);
    k_knn<<<BB * NN / (KNN_WPB * KNN_QPW), KNN_WPB * 32, 0, s2>>>();
    cudaEventRecord(eKnn, s2);

    k_trans_x0<<<dim3(NN / 32, CC / 32, BB), dim3(32, 8)>>>(feats);
    k_mma<true, 128, 128, false, false><<<dim3(NN / 64, 2, BB), 256, MMA_SMEM>>>(
        pW1h, pW1l, pXTh, pXTl, pG1, 256, 0, (size_t)NN * 256, nullptr, nullptr);
    // mma3 x0 partial fills the knn wait window: G3 = W3[:,0:128] * x0
    k_mma<false, 512, 128, false, false><<<dim3(NN / 64, 1, BB), 256, MMA_SMEM>>>(
        pW3h, pW3l, pXTh, pXTl, pG3, 128, 0, (size_t)128 * NN, nullptr, nullptr);

    // join: edge1 needs knn indices
    cudaStreamWaitEvent(0, eKnn, 0);

    k_edge<128><<<dim3(NN / 64, BB), dim3(32, 16)>>>(pG1, pIdx, pM1, pSum1, pSqs1);
    k_normsplit<<<(BB * NN * O1 / 4 + 255) / 256, 256>>>(pM1, pSum1, pSqs1, O1, 128,
                                                         1.0f / (NN * KK));
    // layer 2
    k_mma<true, 128, 128, false, false><<<dim3(NN / 64, 4, BB), 256, MMA_SMEM>>>(
        pW2h, pW2l, pXTh, pXTl, pG2, 512, 128, (size_t)NN * 512, nullptr, nullptr);
    k_edge<256><<<dim3(NN / 64, BB), dim3(64, 8)>>>(pG2, pIdx, pM2, pSum2, pSqs2);
    k_normsplit<<<(BB * NN * O2 / 4 + 255) / 256, 256>>>(pM2, pSum2, pSqs2, O2, 256,
                                                         1.0f / (NN * KK));
    // mma3 tail over K=384 (x1,x2) accumulating onto the x0 partial + fused stats
    k_mma<false, 512, 384, true, true><<<dim3(NN / 64, 1, BB), 256, MMA_SMEM>>>(
        pW3h + 128, pW3l + 128, pXTh, pXTl, pG3, 128, 128, (size_t)128 * NN,
        pSum3, pSqs3);
    k_final<<<(BB * 128 * NN / 4 + 255) / 256, 256>>>(out);
}

// round 17
// speedup vs baseline: 1.1495x; 1.1495x over previous
#include <cuda_runtime.h>
#include <cuda_bf16.h>
#include <cstdint>
#include <cstddef>

// Problem constants
#define BB 2
#define CC 128
#define NN 8192
#define KK 16
#define O1 128
#define O2 256
#define EPSF 1e-5f
#define SLOPE 0.2f

typedef __nv_bfloat16 bf16;

// ---------------- scratch (device globals; no allocation allowed) ----------------
static __device__ float4 g_pts4[BB * NN];
static __device__ int    g_idx[BB * NN * KK];
static __device__ bf16   g_W1h[256 * 128], g_W1l[256 * 128];
static __device__ bf16   g_W2h[512 * 128], g_W2l[512 * 128];
static __device__ bf16   g_W3h[128 * 512], g_W3l[128 * 512];
// unified activation buffer, n-major: [b][n][0:128 x0 | 128:256 x1 | 256:512 x2]
static __device__ bf16   g_XTh[(size_t)BB * NN * 512];
static __device__ bf16   g_XTl[(size_t)BB * NN * 512];
static __device__ float  g_G1[(size_t)BB * NN * 256];
static __device__ float  g_G2[(size_t)BB * NN * 512];
static __device__ float  g_M1[(size_t)BB * NN * 128];
static __device__ float  g_M2[(size_t)BB * NN * 256];
static __device__ float  g_G3[(size_t)BB * 128 * NN];
static __device__ float  g_sum1[BB * O1], g_sqs1[BB * O1];
static __device__ float  g_sum2[BB * O2], g_sqs2[BB * O2];
static __device__ float  g_sum3[BB * 128], g_sqs3[BB * 128];

__device__ __forceinline__ float leakyf(float v) { return v > 0.0f ? v : SLOPE * v; }

__device__ __forceinline__ void bsplit(float v, bf16& h, bf16& l) {
    h = __float2bfloat16(v);
    l = __float2bfloat16(v - __bfloat162float(h));
}

__device__ __forceinline__ void ldsm4(uint32_t* r, uint32_t addr) {
    asm volatile("ldmatrix.sync.aligned.m8n8.x4.shared.b16 {%0,%1,%2,%3}, [%4];"
        : "=r"(r[0]), "=r"(r[1]), "=r"(r[2]), "=r"(r[3]) : "r"(addr));
}

__device__ __forceinline__ void cpa16(uint32_t dst, const void* src) {
    asm volatile("cp.async.cg.shared.global [%0], [%1], 16;" :: "r"(dst), "l"(src));
}
#define CP_COMMIT() asm volatile("cp.async.commit_group;" ::: "memory")

// ---------------- prep: split weights + zero stats + pack points ----------------
__global__ void k_prep(const float* __restrict__ W1, const float* __restrict__ W2,
                       const float* __restrict__ W3, const float* __restrict__ coords) {
    int t = blockIdx.x * blockDim.x + threadIdx.x;
    if (t < 256 * 128) {
        int o = t >> 7, c = t & 127;
        float v = (o < 128) ? (W1[o * 256 + c] - W1[o * 256 + 128 + c])
                            : W1[(o - 128) * 256 + 128 + c];
        bsplit(v, g_W1h[t], g_W1l[t]);
    }
    if (t < 512 * 128) {
        int o = t >> 7, c = t & 127;
        float v = (o < 256) ? (W2[o * 256 + c] - W2[o * 256 + 128 + c])
                            : W2[(o - 256) * 256 + 128 + c];
        bsplit(v, g_W2h[t], g_W2l[t]);
        bsplit(W3[t], g_W3h[t], g_W3l[t]);
    }
    if (t < BB * NN) {
        int b = t >> 13, n = t & (NN - 1);
        const float* base = coords + (size_t)b * 3 * NN;
        float x = base[n], y = base[NN + n], z = base[2 * NN + n];
        g_pts4[t] = make_float4(x, y, z, x * x + y * y + z * z);
    }
    if (t < BB * O1) { g_sum1[t] = 0.0f; g_sqs1[t] = 0.0f; }
    if (t < BB * O2) { g_sum2[t] = 0.0f; g_sqs2[t] = 0.0f; }
    if (t < BB * 128) { g_sum3[t] = 0.0f; g_sqs3[t] = 0.0f; }
}

// ---------------- transpose+split x0: feats [b][c][n] -> XT[b][n][c] ----------------
__global__ void k_trans_x0(const float* __restrict__ feats) {
    __shared__ float t[32][33];
    int b = blockIdx.z, n0 = blockIdx.x * 32, c0 = blockIdx.y * 32;
    int tx = threadIdx.x, ty = threadIdx.y;
#pragma unroll
    for (int i = 0; i < 4; i++) {
        int c = c0 + ty + i * 8;
        t[ty + i * 8][tx] = feats[((size_t)b * CC + c) * NN + n0 + tx];
    }
    __syncthreads();
#pragma unroll
    for (int i = 0; i < 4; i++) {
        int n = n0 + ty + i * 8;
        float v = t[tx][ty + i * 8];
        size_t o = ((size_t)b * NN + n) * 512 + c0 + tx;
        bf16 h, l;
        bsplit(v, h, l);
        g_XTh[o] = h;
        g_XTl[o] = l;
    }
}

// ---------------- warp-collective kNN: 2 queries per warp, 8 warps/block, 1024 tile (R9) ----------------
#define KNN_TS 1024
#define KNN_WPB 8
#define KNN_QPW 2

__global__ void __launch_bounds__(KNN_WPB * 32) k_knn() {
    __shared__ float4 sp[KNN_TS];
    const unsigned FULL = 0xFFFFFFFFu;
    int lane = threadIdx.x & 31;
    int wid = threadIdx.x >> 5;
    int gq0 = (blockIdx.x * KNN_WPB + wid) * KNN_QPW;
    int b = gq0 >> 13;
    int qi0 = gq0 & (NN - 1);

    float4 myq = g_pts4[b * NN + qi0 + (lane & (KNN_QPW - 1))];
    float qx2[KNN_QPW], qy2[KNN_QPW], qz2[KNN_QPW];
    int qid[KNN_QPW];
#pragma unroll
    for (int j = 0; j < KNN_QPW; j++) {
        qx2[j] = -2.0f * __shfl_sync(FULL, myq.x, j);
        qy2[j] = -2.0f * __shfl_sync(FULL, myq.y, j);
        qz2[j] = -2.0f * __shfl_sync(FULL, myq.z, j);
        qid[j] = qi0 + j;
    }

    const float INFF = __int_as_float(0x7f800000);
    float dcur[KNN_QPW]; int icur[KNN_QPW]; float thr[KNN_QPW];
#pragma unroll
    for (int j = 0; j < KNN_QPW; j++) { dcur[j] = INFF; icur[j] = 0; thr[j] = INFF; }

    for (int c0 = 0; c0 < NN; c0 += KNN_TS) {
        __syncthreads();
#pragma unroll
        for (int r = 0; r < KNN_TS / (KNN_WPB * 32); r++)
            sp[r * (KNN_WPB * 32) + threadIdx.x] =
                g_pts4[b * NN + c0 + r * (KNN_WPB * 32) + threadIdx.x];
        __syncthreads();

#pragma unroll 2
        for (int t0 = 0; t0 < KNN_TS; t0 += 32) {
            float4 p = sp[t0 + lane];
            int jg = c0 + t0 + lane;
#pragma unroll
            for (int j = 0; j < KNN_QPW; j++) {
                float d = fmaf(qx2[j], p.x, p.w);
                d = fmaf(qy2[j], p.y, d);
                d = fmaf(qz2[j], p.z, d);
                bool pass = (d < thr[j]) && (jg != qid[j]);
                unsigned m = __ballot_sync(FULL, pass);
                while (m) {
                    int src = __ffs(m) - 1;
                    m &= m - 1;
                    float v = __shfl_sync(FULL, d, src);
                    int  vi = __shfl_sync(FULL, jg, src);
                    if (v < thr[j]) {
                        unsigned stay = __ballot_sync(FULL, (lane < 16) && (dcur[j] <= v));
                        int pos = __popc(stay);
                        float pd = __shfl_up_sync(FULL, dcur[j], 1);
                        int   pi = __shfl_up_sync(FULL, icur[j], 1);
                        if (lane < 16 && lane >= pos) {
                            dcur[j] = (lane == pos) ? v : pd;
                            icur[j] = (lane == pos) ? vi : pi;
                        }
                        thr[j] = __shfl_sync(FULL, dcur[j], 15);
                    }
                }
            }
        }
    }

    if (lane < 16) {
#pragma unroll
        for (int j = 0; j < KNN_QPW; j++)
            g_idx[((size_t)b * NN + qi0 + j) * KK + lane] = icur[j];
    }
}

// ---------------- tensor-core GEMM: 128m x 64n tile, cp.async 3-stage, split-bf16 x3 (R9) ----------------
#define MPAD 40
#define NST 3
#define ASTG (128 * MPAD * 2)          // A stage bytes
#define BSTG (64 * MPAD * 2)           // B stage bytes
#define MMA_SMEM (NST * (ASTG + BSTG)) // 46080 B

template <bool OUTNM, int KD, bool STATS>
__global__ void __launch_bounds__(256) k_mma(
        const bf16* __restrict__ Wh, const bf16* __restrict__ Wl,
        const bf16* __restrict__ Xh, const bf16* __restrict__ Xl,
        float* __restrict__ Out, int M, int kOff, size_t oStride,
        float* __restrict__ sums, float* __restrict__ sqs) {
    constexpr int SL = KD / 32;
    constexpr int TOT = 3 * SL;
    extern __shared__ bf16 dynsm[];
    bf16* As = dynsm;                            // [NST][128][MPAD]
    bf16* Bs = dynsm + NST * 128 * MPAD;         // [NST][64][MPAD]
    __shared__ float sSum[128], sSq[128];

    int tid = threadIdx.x;
    int lane = tid & 31;
    int wid = tid >> 5;
    int wm = wid & 1, wn = wid >> 1;             // warp tile: 64m x 16n
    int b = blockIdx.z;
    int m0 = blockIdx.y * 128, n0 = blockIdx.x * 64;

    int arow = tid >> 1, acolq = (tid & 1) * 16;
    int brow = tid >> 2, bcol = (tid & 3) * 8;
    int lr15 = lane & 15, lh8 = (lane >> 4) * 8;

    uint32_t aBase = (uint32_t)__cvta_generic_to_shared(As);
    uint32_t bBase = (uint32_t)__cvta_generic_to_shared(Bs);
    uint32_t wdst0 = aBase + (arow * MPAD + acolq) * 2;
    uint32_t xdst0 = bBase + (brow * MPAD + bcol) * 2;

    const bf16* wRowH = &Wh[(size_t)(m0 + arow) * KD + acolq];
    const bf16* wRowL = &Wl[(size_t)(m0 + arow) * KD + acolq];
    const bf16* xRowH = &Xh[((size_t)b * NN + n0 + brow) * 512 + kOff + bcol];
    const bf16* xRowL = &Xl[((size_t)b * NN + n0 + brow) * 512 + kOff + bcol];

    auto issue = [&](int s) {
        int seg = s / SL, k0 = (s % SL) * 32;
        const bf16* wsrc = ((seg == 1) ? wRowL : wRowH) + k0;
        const bf16* xsrc = ((seg == 2) ? xRowL : xRowH) + k0;
        uint32_t offA = (uint32_t)((s % NST) * ASTG);
        uint32_t offB = (uint32_t)((s % NST) * BSTG);
        cpa16(wdst0 + offA, wsrc);
        cpa16(wdst0 + offA + 16, wsrc + 8);
        cpa16(xdst0 + offB, xsrc);
    };

    float acc[4][2][4];
#pragma unroll
    for (int i = 0; i < 4; i++)
#pragma unroll
        for (int j = 0; j < 2; j++)
#pragma unroll
            for (int r = 0; r < 4; r++) acc[i][j][r] = 0.0f;

    if (STATS && tid < 128) { sSum[tid] = 0.0f; sSq[tid] = 0.0f; }

    issue(0); CP_COMMIT();
    issue(1); CP_COMMIT();

    for (int s = 0; s < TOT; s++) {
        __syncthreads();                    // buffer (s+2)%NST free (computed at s-1)
        if (s + 2 < TOT) issue(s + 2);
        CP_COMMIT();
        asm volatile("cp.async.wait_group 2;" ::: "memory");   // stage s resident
        __syncthreads();

        uint32_t aB = aBase + (uint32_t)((s % NST) * ASTG);
        uint32_t bB = bBase + (uint32_t)((s % NST) * BSTG);
#pragma unroll
        for (int ks = 0; ks < 2; ks++) {
            uint32_t af[4][4];
#pragma unroll
            for (int i = 0; i < 4; i++) {
                uint32_t addr = aB + ((wm * 64 + i * 16 + lr15) * MPAD + lh8 + ks * 16) * 2;
                ldsm4(af[i], addr);
            }
            uint32_t bfr[4];
            {
                uint32_t addr = bB + ((wn * 16 + lr15) * MPAD + lh8 + ks * 16) * 2;
                ldsm4(bfr, addr);
            }
#pragma unroll
            for (int i = 0; i < 4; i++)
#pragma unroll
                for (int j = 0; j < 2; j++) {
                    asm volatile(
                        "mma.sync.aligned.m16n8k16.row.col.f32.bf16.bf16.f32 "
                        "{%0,%1,%2,%3}, {%4,%5,%6,%7}, {%8,%9}, {%0,%1,%2,%3};"
                        : "+f"(acc[i][j][0]), "+f"(acc[i][j][1]),
                          "+f"(acc[i][j][2]), "+f"(acc[i][j][3])
                        : "r"(af[i][0]), "r"(af[i][1]), "r"(af[i][2]), "r"(af[i][3]),
                          "r"(bfr[j]), "r"(bfr[j + 2]));
                }
        }
    }

    int g = lane >> 2, tq = lane & 3;
    float* Ob = Out + (size_t)b * oStride;
    if (OUTNM) {
#pragma unroll
        for (int i = 0; i < 4; i++) {
            int m = m0 + wm * 64 + i * 16 + g;
#pragma unroll
            for (int j = 0; j < 2; j++) {
                int n = n0 + wn * 16 + j * 8 + 2 * tq;
                Ob[(size_t)n * M + m] = acc[i][j][0];
                Ob[(size_t)(n + 1) * M + m] = acc[i][j][1];
                Ob[(size_t)n * M + m + 8] = acc[i][j][2];
                Ob[(size_t)(n + 1) * M + m + 8] = acc[i][j][3];
            }
        }
    } else {
#pragma unroll
        for (int i = 0; i < 4; i++) {
            int m = m0 + wm * 64 + i * 16 + g;
#pragma unroll
            for (int j = 0; j < 2; j++) {
                int n = n0 + wn * 16 + j * 8 + 2 * tq;
                *(float2*)&Ob[(size_t)m * NN + n] = make_float2(acc[i][j][0], acc[i][j][1]);
                *(float2*)&Ob[(size_t)(m + 8) * NN + n] = make_float2(acc[i][j][2], acc[i][j][3]);
            }
        }
    }

    if (STATS) {
        const unsigned FULL = 0xFFFFFFFFu;
#pragma unroll
        for (int i = 0; i < 4; i++) {
            float s0 = 0.0f, q0 = 0.0f, s1 = 0.0f, q1 = 0.0f;
#pragma unroll
            for (int j = 0; j < 2; j++) {
                float a0 = acc[i][j][0], a1 = acc[i][j][1];
                float a2 = acc[i][j][2], a3 = acc[i][j][3];
                s0 += a0 + a1;
                q0 = fmaf(a0, a0, q0); q0 = fmaf(a1, a1, q0);
                s1 += a2 + a3;
                q1 = fmaf(a2, a2, q1); q1 = fmaf(a3, a3, q1);
            }
#pragma unroll
            for (int sh = 1; sh < 4; sh <<= 1) {
                s0 += __shfl_xor_sync(FULL, s0, sh);
                q0 += __shfl_xor_sync(FULL, q0, sh);
                s1 += __shfl_xor_sync(FULL, s1, sh);
                q1 += __shfl_xor_sync(FULL, q1, sh);
            }
            if (tq == 0) {
                int r = wm * 64 + i * 16 + g;
                atomicAdd(&sSum[r], s0);
                atomicAdd(&sSq[r], q0);
                atomicAdd(&sSum[r + 8], s1);
                atomicAdd(&sSq[r + 8], q1);
            }
        }
        __syncthreads();
        if (tid < 128) {
            atomicAdd(&sums[b * 128 + m0 + tid], sSum[tid]);
            atomicAdd(&sqs[b * 128 + m0 + tid], sSq[tid]);
        }
    }
}

// ---------------- edge layer (float4): y = A[n,:] + B[idx[n,k],:]; max over k + stats ----------------
template <int O>
__global__ void k_edge(const float* __restrict__ G, const int* __restrict__ idx,
                       float* __restrict__ Mout, float* __restrict__ sums,
                       float* __restrict__ sqs) {
    constexpr int TX = O / 4;
    constexpr int TY = 512 / TX;
    constexpr int NPB = 64;
    int b = blockIdx.y;
    int n0 = blockIdx.x * NPB;
    int tx = threadIdx.x, ty = threadIdx.y;
    float4 lsum = make_float4(0, 0, 0, 0), lsq = make_float4(0, 0, 0, 0);
    const float NEGINF = __int_as_float(0xff800000);

    for (int n = n0 + ty; n < n0 + NPB; n += TY) {
        size_t rowb = (size_t)b * NN + n;
        float4 a = *(const float4*)&G[rowb * (2 * O) + 4 * tx];
        const int4* I4 = (const int4*)(idx + rowb * KK);
        int4 iv[4] = { I4[0], I4[1], I4[2], I4[3] };
        const int* I = (const int*)iv;
        float4 mx = make_float4(NEGINF, NEGINF, NEGINF, NEGINF);
#pragma unroll
        for (int k = 0; k < KK; k++) {
            int j = I[k];
            float4 bv = *(const float4*)&G[((size_t)b * NN + j) * (2 * O) + O + 4 * tx];
            float4 v = make_float4(a.x + bv.x, a.y + bv.y, a.z + bv.z, a.w + bv.w);
            mx.x = fmaxf(mx.x, v.x); mx.y = fmaxf(mx.y, v.y);
            mx.z = fmaxf(mx.z, v.z); mx.w = fmaxf(mx.w, v.w);
            lsum.x += v.x; lsum.y += v.y; lsum.z += v.z; lsum.w += v.w;
            lsq.x = fmaf(v.x, v.x, lsq.x); lsq.y = fmaf(v.y, v.y, lsq.y);
            lsq.z = fmaf(v.z, v.z, lsq.z); lsq.w = fmaf(v.w, v.w, lsq.w);
        }
        *(float4*)&Mout[rowb * O + 4 * tx] = mx;
    }
    __shared__ float4 s1[TY][TX], s2[TY][TX];
    s1[ty][tx] = lsum; s2[ty][tx] = lsq;
    __syncthreads();
    if (ty == 0) {
        float4 t1 = lsum, t2 = lsq;
#pragma unroll
        for (int t = 1; t < TY; t++) {
            float4 u1 = s1[t][tx], u2 = s2[t][tx];
            t1.x += u1.x; t1.y += u1.y; t1.z += u1.z; t1.w += u1.w;
            t2.x += u2.x; t2.y += u2.y; t2.z += u2.z; t2.w += u2.w;
        }
        atomicAdd(&sums[b * O + 4 * tx + 0], t1.x);
        atomicAdd(&sums[b * O + 4 * tx + 1], t1.y);
        atomicAdd(&sums[b * O + 4 * tx + 2], t1.z);
        atomicAdd(&sums[b * O + 4 * tx + 3], t1.w);
        atomicAdd(&sqs[b * O + 4 * tx + 0], t2.x);
        atomicAdd(&sqs[b * O + 4 * tx + 1], t2.y);
        atomicAdd(&sqs[b * O + 4 * tx + 2], t2.z);
        atomicAdd(&sqs[b * O + 4 * tx + 3], t2.w);
    }
}

// ---------------- normalize + leaky + bf16-split (stats inline): Min[b][n][O] -> XT ----------------
__global__ void k_normsplit(const float* __restrict__ Min, const float* __restrict__ sums,
                            const float* __restrict__ sqs, int O, int obase, float invcnt) {
    size_t t = (size_t)blockIdx.x * blockDim.x + threadIdx.x;
    if (t >= (size_t)BB * NN * O / 4) return;
    int o4 = (int)(t % (O / 4));
    size_t bn = t / (O / 4);
    int b = (int)(bn >> 13);
    float4 v = ((const float4*)Min)[t];
    float vv[4] = { v.x, v.y, v.z, v.w };
    bf16 h4[4], l4[4];
#pragma unroll
    for (int c = 0; c < 4; c++) {
        int o = 4 * o4 + c;
        float m = sums[b * O + o] * invcnt;
        float var = sqs[b * O + o] * invcnt - m * m;
        float iv = rsqrtf(var + EPSF);
        float y = leakyf((vv[c] - m) * iv);
        bsplit(y, h4[c], l4[c]);
    }
    size_t dst = bn * 512 + obase + 4 * o4;
    *(uint2*)&g_XTh[dst] = *(uint2*)h4;
    *(uint2*)&g_XTl[dst] = *(uint2*)l4;
}

// ---------------- final normalize + leaky -> output [B,C,N] ----------------
__global__ void k_final(float* __restrict__ out) {
    size_t t = (size_t)blockIdx.x * blockDim.x + threadIdx.x;
    if (t >= (size_t)BB * 128 * NN / 4) return;
    int bo = (int)(t / (NN / 4));
    float m = g_sum3[bo] * (1.0f / NN);
    float var = g_sqs3[bo] * (1.0f / NN) - m * m;
    float iv = rsqrtf(var + EPSF);
    float4 v = ((const float4*)g_G3)[t];
    v.x = leakyf((v.x - m) * iv);
    v.y = leakyf((v.y - m) * iv);
    v.z = leakyf((v.z - m) * iv);
    v.w = leakyf((v.w - m) * iv);
    ((float4*)out)[t] = v;
}

// ---------------- launch ----------------
extern "C" void kernel_launch(void* const* d_in, const int* in_sizes, int n_in,
                              void* d_out, int out_size) {
    const float* coords = (const float*)d_in[0];
    const float* feats  = (const float*)d_in[1];
    const float* W1     = (const float*)d_in[2];
    const float* W2     = (const float*)d_in[3];
    const float* W3     = (const float*)d_in[4];
    float* out = (float*)d_out;

    cudaFuncSetAttribute(k_knn, cudaFuncAttributePreferredSharedMemoryCarveout,
                         cudaSharedmemCarveoutMaxShared);
    cudaFuncSetAttribute(k_mma<true, 128, false>,
                         cudaFuncAttributeMaxDynamicSharedMemorySize, MMA_SMEM);
    cudaFuncSetAttribute(k_mma<false, 512, true>,
                         cudaFuncAttributeMaxDynamicSharedMemorySize, MMA_SMEM);

    float *pG1, *pG2, *pM1, *pM2, *pG3;
    int* pIdx;
    float *pSum1, *pSqs1, *pSum2, *pSqs2, *pSum3, *pSqs3;
    bf16 *pW1h, *pW1l, *pW2h, *pW2l, *pW3h, *pW3l, *pXTh, *pXTl;
    cudaGetSymbolAddress((void**)&pG1, g_G1);
    cudaGetSymbolAddress((void**)&pG2, g_G2);
    cudaGetSymbolAddress((void**)&pM1, g_M1);
    cudaGetSymbolAddress((void**)&pM2, g_M2);
    cudaGetSymbolAddress((void**)&pG3, g_G3);
    cudaGetSymbolAddress((void**)&pIdx, g_idx);
    cudaGetSymbolAddress((void**)&pSum1, g_sum1);
    cudaGetSymbolAddress((void**)&pSqs1, g_sqs1);
    cudaGetSymbolAddress((void**)&pSum2, g_sum2);
    cudaGetSymbolAddress((void**)&pSqs2, g_sqs2);
    cudaGetSymbolAddress((void**)&pSum3, g_sum3);
    cudaGetSymbolAddress((void**)&pSqs3, g_sqs3);
    cudaGetSymbolAddress((void**)&pW1h, g_W1h);
    cudaGetSymbolAddress((void**)&pW1l, g_W1l);
    cudaGetSymbolAddress((void**)&pW2h, g_W2h);
    cudaGetSymbolAddress((void**)&pW2l, g_W2l);
    cudaGetSymbolAddress((void**)&pW3h, g_W3h);
    cudaGetSymbolAddress((void**)&pW3l, g_W3l);
    cudaGetSymbolAddress((void**)&pXTh, g_XTh);
    cudaGetSymbolAddress((void**)&pXTl, g_XTl);
    (void)in_sizes; (void)n_in; (void)out_size;

    // side stream + events for a parallel knn branch in the captured graph
    cudaStream_t s2;
    cudaEvent_t eFork, eKnn;
    cudaStreamCreateWithFlags(&s2, cudaStreamNonBlocking);
    cudaEventCreateWithFlags(&eFork, cudaEventDisableTiming);
    cudaEventCreateWithFlags(&eKnn, cudaEventDisableTiming);

    k_prep<<<256, 256>>>(W1, W2, W3, coords);

    // fork: knn runs concurrently with trans_x0 + layer-1 MMA
    cudaEventRecord(eFork, 0);
    cudaStreamWaitEvent(s2, eFork, 0);
    k_knn<<<BB * NN / (KNN_WPB * KNN_QPW), KNN_WPB * 32, 0, s2>>>();
    cudaEventRecord(eKnn, s2);

    k_trans_x0<<<dim3(NN / 32, CC / 32, BB), dim3(32, 8)>>>(feats);
    k_mma<true, 128, false><<<dim3(NN / 64, 2, BB), 256, MMA_SMEM>>>(
        pW1h, pW1l, pXTh, pXTl, pG1, 256, 0, (size_t)NN * 256, nullptr, nullptr);

    // join: edge1 needs knn indices
    cudaStreamWaitEvent(0, eKnn, 0);

    k_edge<128><<<dim3(NN / 64, BB), dim3(32, 16)>>>(pG1, pIdx, pM1, pSum1, pSqs1);
    k_normsplit<<<(BB * NN * O1 / 4 + 255) / 256, 256>>>(pM1, pSum1, pSqs1, O1, 128,
                                                         1.0f / (NN * KK));
    // layer 2
    k_mma<true, 128, false><<<dim3(NN / 64, 4, BB), 256, MMA_SMEM>>>(
        pW2h, pW2l, pXTh, pXTl, pG2, 512, 128, (size_t)NN * 512, nullptr, nullptr);
    k_edge<256><<<dim3(NN / 64, BB), dim3(64, 8)>>>(pG2, pIdx, pM2, pSum2, pSqs2);
    k_normsplit<<<(BB * NN * O2 / 4 + 255) / 256, 256>>>(pM2, pSum2, pSqs2, O2, 256,
                                                         1.0f / (NN * KK));
    // layer 3: MMA + fused instance-norm stats
    k_mma<false, 512, true><<<dim3(NN / 64, 1, BB), 256, MMA_SMEM>>>(
        pW3h, pW3l, pXTh, pXTl, pG3, 128, 0, (size_t)128 * NN, pSum3, pSqs3);
    k_final<<<(BB * 128 * NN / 4 + 255) / 256, 256>>>(out);
}